// round 2
// baseline (speedup 1.0000x reference)
#include <cuda_runtime.h>

// Problem constants (match reference)
#define MP      64000          // pillars
#define PP      32             // points per pillar
#define COUT    64
#define BB      4
#define YL      496
#define XL      432
#define HW      (YL * XL)      // 214272
#define NCELL   (BB * HW)      // 857088
#define BN_EPS  1e-3f
#define VXY     0.16f
#define XOFF    0.08f          // VX/2 + X0
#define YOFF    (-39.6f)       // VY/2 + Y0

// Scratch (allocation-free: device globals)
__device__ int   g_winner[NCELL];
__device__ float g_pooled[MP * COUT];

// ---------------------------------------------------------------------------
// K1: winner map init
// ---------------------------------------------------------------------------
__global__ void k_init_winner() {
    int i = blockIdx.x * blockDim.x + threadIdx.x;
    if (i < NCELL) g_winner[i] = -1;
}

// ---------------------------------------------------------------------------
// K2: per-pillar feature build + 9->64 GEMM + BN + ReLU + max-pool
//     one warp per pillar; lane = point for the feature phase,
//     lane = channel pair (lane, lane+32) for the GEMM phase.
//     Also resolves scatter duplicates via atomicMax on pillar index
//     (XLA sequential scatter: last update wins).
// ---------------------------------------------------------------------------
__global__ __launch_bounds__(256) void k_pillar(
    const float* __restrict__ pillars,   // [M, 32, 4]
    const int*   __restrict__ coors,     // [M, 4] (b, z, y, x)
    const int*   __restrict__ nums,      // [M]
    const float* __restrict__ W,         // [64, 9]
    const float* __restrict__ gamma,
    const float* __restrict__ beta,
    const float* __restrict__ rmean,
    const float* __restrict__ rvar,
    int M)
{
    __shared__ float sfeat[8][PP][9];

    const int warp = threadIdx.x >> 5;
    const int lane = threadIdx.x & 31;
    const int m    = blockIdx.x * 8 + warp;
    if (m >= M) return;

    const int num = nums[m];

    // --- feature phase: lane == point index ---
    float4 pt = reinterpret_cast<const float4*>(pillars)[m * PP + lane];

    const bool vmask = (lane < num);
    float sx = vmask ? pt.x : 0.f;
    float sy = vmask ? pt.y : 0.f;
    float sz = vmask ? pt.z : 0.f;
    #pragma unroll
    for (int o = 16; o > 0; o >>= 1) {
        sx += __shfl_xor_sync(0xffffffffu, sx, o);
        sy += __shfl_xor_sync(0xffffffffu, sy, o);
        sz += __shfl_xor_sync(0xffffffffu, sz, o);
    }
    const float inv = 1.f / (float)num;   // num >= 1
    const float mx = sx * inv, my = sy * inv, mz = sz * inv;

    const int cb = coors[m * 4 + 0];
    const int cy = coors[m * 4 + 2];
    const int cx = coors[m * 4 + 3];
    const float xc = (float)cx * VXY + XOFF;
    const float yc = (float)cy * VXY + YOFF;

    float* sf = &sfeat[warp][lane][0];
    sf[0] = pt.x;      sf[1] = pt.y;      sf[2] = pt.z;      sf[3] = pt.w;
    sf[4] = pt.x - mx; sf[5] = pt.y - my; sf[6] = pt.z - mz;
    sf[7] = pt.x - xc; sf[8] = pt.y - yc;
    __syncwarp();

    // --- GEMM phase: lane owns channels (lane, lane+32) ---
    const int o0 = lane, o1 = lane + 32;
    float w0[9], w1[9];
    #pragma unroll
    for (int c = 0; c < 9; c++) {
        w0[c] = __ldg(&W[o0 * 9 + c]);
        w1[c] = __ldg(&W[o1 * 9 + c]);
    }
    const float s0 = __ldg(&gamma[o0]) * rsqrtf(__ldg(&rvar[o0]) + BN_EPS);
    const float s1 = __ldg(&gamma[o1]) * rsqrtf(__ldg(&rvar[o1]) + BN_EPS);
    const float b0 = __ldg(&beta[o0]) - __ldg(&rmean[o0]) * s0;
    const float b1 = __ldg(&beta[o1]) - __ldg(&rmean[o1]) * s1;

    // Masked (p >= num) points contribute relu(bias); present iff num < 32.
    // All candidates are >= 0 after relu, so seed with max(bias, 0) / 0 and
    // fold relu into the running max (valid since seed >= 0).
    float max0 = (num < PP) ? fmaxf(b0, 0.f) : 0.f;
    float max1 = (num < PP) ? fmaxf(b1, 0.f) : 0.f;

    const float (*fp)[9] = sfeat[warp];
    for (int p = 0; p < num; p++) {
        float h0 = 0.f, h1 = 0.f;
        #pragma unroll
        for (int c = 0; c < 9; c++) {
            const float fv = fp[p][c];
            h0 = fmaf(fv, w0[c], h0);
            h1 = fmaf(fv, w1[c], h1);
        }
        max0 = fmaxf(max0, fmaf(h0, s0, b0));
        max1 = fmaxf(max1, fmaf(h1, s1, b1));
    }

    g_pooled[m * COUT + o0] = max0;
    g_pooled[m * COUT + o1] = max1;

    if (lane == 0 &&
        (unsigned)cx < (unsigned)XL &&
        (unsigned)cy < (unsigned)YL &&
        (unsigned)cb < (unsigned)BB) {
        atomicMax(&g_winner[(cb * YL + cy) * XL + cx], m);
    }
}

// ---------------------------------------------------------------------------
// K3: output-stationary canvas fill (NCHW). Channel-outer loop keeps the
//     219MB of stores coalesced; pooled gather only on winner cells (~7%).
// ---------------------------------------------------------------------------
__global__ __launch_bounds__(256) void k_fill(float* __restrict__ out) {
    const int cell = blockIdx.x * blockDim.x + threadIdx.x;
    if (cell >= NCELL) return;

    const int w  = g_winner[cell];
    const int b  = cell / HW;
    const int yx = cell - b * HW;

    float* op = out + (size_t)b * COUT * HW + yx;
    const float* pp = g_pooled + (size_t)(w < 0 ? 0 : w) * COUT;

    #pragma unroll
    for (int c = 0; c < COUT; c++) {
        op[(size_t)c * HW] = (w >= 0) ? __ldg(&pp[c]) : 0.f;
    }
}

// ---------------------------------------------------------------------------
extern "C" void kernel_launch(void* const* d_in, const int* in_sizes, int n_in,
                              void* d_out, int out_size)
{
    const float* pillars = (const float*)d_in[0];
    const int*   coors   = (const int*)  d_in[1];
    const int*   nums    = (const int*)  d_in[2];
    const float* W       = (const float*)d_in[3];
    const float* gamma   = (const float*)d_in[4];
    const float* beta    = (const float*)d_in[5];
    const float* rmean   = (const float*)d_in[6];
    const float* rvar    = (const float*)d_in[7];
    float* out = (float*)d_out;

    const int M = in_sizes[0] / (PP * 4);

    k_init_winner<<<(NCELL + 255) / 256, 256>>>();
    k_pillar<<<(M + 7) / 8, 256>>>(pillars, coors, nums, W,
                                   gamma, beta, rmean, rvar, M);
    k_fill<<<(NCELL + 255) / 256, 256>>>(out);
}